// round 6
// baseline (speedup 1.0000x reference)
#include <cuda_runtime.h>

// Scratch (no allocation allowed -> __device__ globals)
__device__ float2 g_A[16*64*256*32];   // [bc][h][ky]      67 MB
__device__ float2 g_X[16*32*32*64];    // [b][mode][c]     8.4 MB
__device__ float2 g_M[16*64*32*32];    // [bo][kx][ky]     8.4 MB
__device__ float2 g_T[16*64*256*32];   // [bo][h][ky]      67 MB

// Compile-time twiddles: cos/sin(2*pi*k/256) as exact fp32 literals so ptxas
// can emit FFMA with an immediate multiplier (rt_SMSP=1 vs 2 for 3-reg form).
__host__ __device__ constexpr float TWC(int k) {
    k &= 255;
    if (k > 128) k = 256 - k;               // cos symmetry
    double x = 6.283185307179586476925286766559 * (double)k / 256.0;
    double x2 = x * x, t = 1.0, s = 1.0;
    for (int i = 1; i <= 24; i++) { t *= -x2 / ((2.0*i - 1.0) * (2.0*i)); s += t; }
    return (float)s;
}
__host__ __device__ constexpr float TWS(int k) { return TWC(k - 64); }   // sin

// Device-safe compile-time unroll (no std::integral_constant operator int)
template<int I> struct ic { static constexpr int v = I; };
template<class F, int... Is>
__device__ __forceinline__ void unroll_(F&& f, ic<Is>...) { (f(ic<Is>{}), ...); }
template<int N, class F, int... Is>
__device__ __forceinline__ void unroll_build(F&& f, ic<Is>... tags) {
    if constexpr (sizeof...(Is) == N) { (f(tags), ...); }
    else unroll_build<N>(static_cast<F&&>(f), tags..., ic<sizeof...(Is)>{});
}
// Simpler: recursive unroll
template<int I, int N, class F>
__device__ __forceinline__ void unroll_rec(F&& f) {
    if constexpr (I < N) { f(ic<I>{}); unroll_rec<I + 1, N>(static_cast<F&&>(f)); }
}
template<int N, class F>
__device__ __forceinline__ void unroll(F&& f) { unroll_rec<0, N>(static_cast<F&&>(f)); }

// ---------------------------------------------------------------------------
// K1: forward W-transform, hermitian input fold, imm twiddles.
//   A[h,ky] = (1/256)[ x0 + sum_{p=1..128} xp[p] c(ky p) - i xm[p] s(ky p) ]
// block 256 = 8 warps x 4 ky (template); lane = h. grid (1024 bc, 8 h-tiles).
// ---------------------------------------------------------------------------
template<int KY0>
__device__ __forceinline__ void k1_body(const float* __restrict__ sp,
                                        const float* __restrict__ sm,
                                        int lane, float ar[4], float ai[4]) {
    unroll<128>([&](auto pc) {
        constexpr int P = decltype(pc)::v + 1;
        float xp = sp[(P - 1) * 33 + lane];
        float xm = sm[(P - 1) * 33 + lane];
        unroll<4>([&](auto kc) {
            constexpr int KI = decltype(kc)::v;
            constexpr int KY = KY0 + KI;
            constexpr float C = TWC(KY * P);
            constexpr float S = -TWS(KY * P);
            ar[KI] = fmaf(xp, C, ar[KI]);
            ai[KI] = fmaf(xm, S, ai[KI]);
        });
    });
}

__global__ __launch_bounds__(256) void k_fwdW(const float* __restrict__ x) {
    __shared__ float sp[128 * 33], sm[128 * 33], sx0[32];
    int bc = blockIdx.x, h0 = blockIdx.y * 32;
    const float* xr = x + (size_t)bc * 65536 + (size_t)h0 * 256;

    for (int i = threadIdx.x; i < 4096; i += 256) {
        int f = i & 127, h = i >> 7;
        float a = xr[h * 256 + f + 1];
        float b = xr[h * 256 + 255 - f];
        sp[f * 33 + h] = (f == 127) ? a   : a + b;
        sm[f * 33 + h] = (f == 127) ? 0.f : a - b;
    }
    if (threadIdx.x < 32) sx0[threadIdx.x] = xr[threadIdx.x * 256];
    __syncthreads();

    int lane = threadIdx.x & 31, wrp = threadIdx.x >> 5;
    float x0 = sx0[lane];
    float ar[4], ai[4];
    #pragma unroll
    for (int k = 0; k < 4; k++) { ar[k] = x0; ai[k] = 0.f; }

    switch (wrp) {
        case 0: k1_body<0 >(sp, sm, lane, ar, ai); break;
        case 1: k1_body<4 >(sp, sm, lane, ar, ai); break;
        case 2: k1_body<8 >(sp, sm, lane, ar, ai); break;
        case 3: k1_body<12>(sp, sm, lane, ar, ai); break;
        case 4: k1_body<16>(sp, sm, lane, ar, ai); break;
        case 5: k1_body<20>(sp, sm, lane, ar, ai); break;
        case 6: k1_body<24>(sp, sm, lane, ar, ai); break;
        default:k1_body<28>(sp, sm, lane, ar, ai); break;
    }

    const float sc = 1.0f / 256.0f;   // ortho forward
    float2* A = &g_A[(size_t)bc * 8192];
    #pragma unroll
    for (int k = 0; k < 4; k++)
        A[(h0 + lane) * 32 + wrp * 4 + k] = make_float2(ar[k] * sc, ai[k] * sc);
}

// ---------------------------------------------------------------------------
// K2: forward H-transform, h-parity fold (P = A[h]+A[h+128], Q = A[h]-A[h+128]):
//   X[kx] = sum_{h<128} D[h] e^{-2pi i kx h/256},  D = P if kx even else Q.
// block 256 = 8 warps x 4 kx (template); lane = ky. grid 1024 bc.
// ---------------------------------------------------------------------------
template<int KX0>
__device__ __forceinline__ void k2_body(const float2* __restrict__ sP,
                                        const float2* __restrict__ sQ,
                                        int lane, float xre[4], float xim[4]) {
    unroll<128>([&](auto hc) {
        constexpr int H = decltype(hc)::v;
        float2 p = sP[H * 32 + lane];
        float2 q = sQ[H * 32 + lane];
        unroll<4>([&](auto kc) {
            constexpr int KI = decltype(kc)::v;
            constexpr int KX = KX0 + KI;
            constexpr float C = TWC(KX * H);
            constexpr float S = TWS(KX * H);
            float dr = (KX & 1) ? q.x : p.x;
            float di = (KX & 1) ? q.y : p.y;
            // (dr + i di)(C - i S)
            xre[KI] = fmaf(dr, C, fmaf(di,  S, xre[KI]));
            xim[KI] = fmaf(di, C, fmaf(dr, -S, xim[KI]));
        });
    });
}

__global__ __launch_bounds__(256, 2) void k_fwdH() {
    __shared__ float2 sP[128 * 32], sQ[128 * 32];   // 64 KB
    int bc = blockIdx.x;
    const float2* A = &g_A[(size_t)bc * 8192];

    for (int i = threadIdx.x; i < 4096; i += 256) {
        int ky = i & 31, h = i >> 5;
        float2 a = A[h * 32 + ky];
        float2 b = A[(h + 128) * 32 + ky];
        sP[h * 32 + ky] = make_float2(a.x + b.x, a.y + b.y);
        sQ[h * 32 + ky] = make_float2(a.x - b.x, a.y - b.y);
    }
    __syncthreads();

    int lane = threadIdx.x & 31, wrp = threadIdx.x >> 5;
    float xre[4] = {0,0,0,0}, xim[4] = {0,0,0,0};
    switch (wrp) {
        case 0: k2_body<0 >(sP, sQ, lane, xre, xim); break;
        case 1: k2_body<4 >(sP, sQ, lane, xre, xim); break;
        case 2: k2_body<8 >(sP, sQ, lane, xre, xim); break;
        case 3: k2_body<12>(sP, sQ, lane, xre, xim); break;
        case 4: k2_body<16>(sP, sQ, lane, xre, xim); break;
        case 5: k2_body<20>(sP, sQ, lane, xre, xim); break;
        case 6: k2_body<24>(sP, sQ, lane, xre, xim); break;
        default:k2_body<28>(sP, sQ, lane, xre, xim); break;
    }

    int b = bc >> 6, c = bc & 63;
    #pragma unroll
    for (int k = 0; k < 4; k++)
        g_X[((size_t)b * 1024 + (wrp * 4 + k) * 32 + lane) * 64 + c] =
            make_float2(xre[k], xim[k]);
}

// ---------------------------------------------------------------------------
// K3: channel mix.  M[b,o,m] = sum_c X[b,c,m] * (Wr + i Wi)[c,o,m]
// ---------------------------------------------------------------------------
__global__ __launch_bounds__(256) void k_mix(const float* __restrict__ wr,
                                             const float* __restrict__ wi) {
    int m = blockIdx.x;
    __shared__ float2 Ws[64 * 64];
    __shared__ float2 Xs[16 * 64];

    for (int i = threadIdx.x; i < 4096; i += 256)
        Ws[i] = make_float2(wr[(size_t)i * 1024 + m], wi[(size_t)i * 1024 + m]);
    for (int i = threadIdx.x; i < 1024; i += 256) {
        int b = i >> 6, c = i & 63;
        Xs[i] = g_X[((size_t)b * 1024 + m) * 64 + c];
    }
    __syncthreads();

    #pragma unroll
    for (int k = 0; k < 4; k++) {
        int idx = threadIdx.x + k * 256;
        int b = idx >> 6, o = idx & 63;
        float accr = 0.f, acci = 0.f;
        #pragma unroll 8
        for (int c = 0; c < 64; c++) {
            float2 X  = Xs[b * 64 + c];
            float2 Wv = Ws[c * 64 + o];
            accr = fmaf(X.x, Wv.x, fmaf(-X.y, Wv.y, accr));
            acci = fmaf(X.x, Wv.y, fmaf( X.y, Wv.x, acci));
        }
        g_M[((size_t)b * 64 + o) * 1024 + m] = make_float2(accr, acci);
    }
}

// ---------------------------------------------------------------------------
// K4: inverse H-transform, kx-parity fold (E even kx, Q odd kx):
//   T[h] = (E+Q)*s,  T[h+128] = (E-Q)*s,  s = (ky==0?1:2)/256.
// block 256 = 8 warps x 16 h (template); lane = ky. grid 1024 bo.
// ---------------------------------------------------------------------------
template<int H0>
__device__ __forceinline__ void k4_body(const float2* __restrict__ Ms, int lane,
                                        float Er[16], float Ei[16],
                                        float Qr[16], float Qi[16]) {
    unroll<32>([&](auto xc) {
        constexpr int KX = decltype(xc)::v;
        float2 m = Ms[KX * 32 + lane];
        unroll<16>([&](auto hc) {
            constexpr int HI = decltype(hc)::v;
            constexpr int H = H0 + HI;
            constexpr float C = TWC(KX * H);
            constexpr float S = TWS(KX * H);
            // (Mr + i Mi)(C + i S)
            if constexpr (KX & 1) {
                Qr[HI] = fmaf(m.x, C, fmaf(m.y, -S, Qr[HI]));
                Qi[HI] = fmaf(m.x, S, fmaf(m.y,  C, Qi[HI]));
            } else {
                Er[HI] = fmaf(m.x, C, fmaf(m.y, -S, Er[HI]));
                Ei[HI] = fmaf(m.x, S, fmaf(m.y,  C, Ei[HI]));
            }
        });
    });
}

__global__ __launch_bounds__(256, 2) void k_invH() {
    __shared__ float2 Ms[1024];
    int bo = blockIdx.x;
    for (int i = threadIdx.x; i < 1024; i += 256)
        Ms[i] = g_M[(size_t)bo * 1024 + i];
    __syncthreads();

    int lane = threadIdx.x & 31, wrp = threadIdx.x >> 5;
    float Er[16] = {}, Ei[16] = {}, Qr[16] = {}, Qi[16] = {};
    switch (wrp) {
        case 0: k4_body<0  >(Ms, lane, Er, Ei, Qr, Qi); break;
        case 1: k4_body<16 >(Ms, lane, Er, Ei, Qr, Qi); break;
        case 2: k4_body<32 >(Ms, lane, Er, Ei, Qr, Qi); break;
        case 3: k4_body<48 >(Ms, lane, Er, Ei, Qr, Qi); break;
        case 4: k4_body<64 >(Ms, lane, Er, Ei, Qr, Qi); break;
        case 5: k4_body<80 >(Ms, lane, Er, Ei, Qr, Qi); break;
        case 6: k4_body<96 >(Ms, lane, Er, Ei, Qr, Qi); break;
        default:k4_body<112>(Ms, lane, Er, Ei, Qr, Qi); break;
    }

    float s = (lane == 0 ? 1.0f : 2.0f) * (1.0f / 256.0f);
    float2* T = &g_T[(size_t)bo * 8192];
    int hb = wrp * 16;
    #pragma unroll
    for (int j = 0; j < 16; j++) {
        int h = hb + j;
        T[h * 32 + lane]         = make_float2((Er[j] + Qr[j]) * s, (Ei[j] + Qi[j]) * s);
        T[(h + 128) * 32 + lane] = make_float2((Er[j] - Qr[j]) * s, (Ei[j] - Qi[j]) * s);
    }
}

// ---------------------------------------------------------------------------
// K5: inverse W-transform, output fold over (w, 256-w):
//   U = sum_ky TR c(ky w), V = sum_ky TI s(ky w); out[w]=U-V, out[256-w]=U+V;
//   out[128] = sum_ky TR (-1)^ky  (warp 0 extra accumulator).
// block 256 = 8 warps x 16 w (template); lane = h. grid (1024 bo, 8 h-tiles).
// ---------------------------------------------------------------------------
template<int W0>
__device__ __forceinline__ void k5_body(const float* __restrict__ TsR,
                                        const float* __restrict__ TsI,
                                        int lane, float U[16], float V[16],
                                        float& U128) {
    unroll<32>([&](auto yc) {
        constexpr int KY = decltype(yc)::v;
        float tr = TsR[lane * 33 + KY];
        float ti = TsI[lane * 33 + KY];
        unroll<16>([&](auto wc) {
            constexpr int WI = decltype(wc)::v;
            constexpr int W = W0 + WI;
            constexpr float C = TWC(KY * W);
            constexpr float S = TWS(KY * W);
            U[WI] = fmaf(tr, C, U[WI]);
            V[WI] = fmaf(ti, S, V[WI]);
        });
        if constexpr (W0 == 0) {
            constexpr float C128 = TWC(128 * KY);
            U128 = fmaf(tr, C128, U128);
        }
    });
}

__global__ __launch_bounds__(256) void k_invW(float* __restrict__ out) {
    __shared__ float TsR[32 * 33], TsI[32 * 33];
    __shared__ float Os[32 * 257];
    int bo = blockIdx.x, h0 = blockIdx.y * 32;

    const float2* T = &g_T[((size_t)bo * 256 + h0) * 32];
    for (int i = threadIdx.x; i < 1024; i += 256) {
        int ky = i & 31, h = i >> 5;
        float2 t = T[h * 32 + ky];
        TsR[h * 33 + ky] = t.x;
        TsI[h * 33 + ky] = t.y;
    }
    __syncthreads();

    int lane = threadIdx.x & 31, wrp = threadIdx.x >> 5;
    float U[16] = {}, V[16] = {}, U128 = 0.f;
    switch (wrp) {
        case 0: k5_body<0  >(TsR, TsI, lane, U, V, U128); break;
        case 1: k5_body<16 >(TsR, TsI, lane, U, V, U128); break;
        case 2: k5_body<32 >(TsR, TsI, lane, U, V, U128); break;
        case 3: k5_body<48 >(TsR, TsI, lane, U, V, U128); break;
        case 4: k5_body<64 >(TsR, TsI, lane, U, V, U128); break;
        case 5: k5_body<80 >(TsR, TsI, lane, U, V, U128); break;
        case 6: k5_body<96 >(TsR, TsI, lane, U, V, U128); break;
        default:k5_body<112>(TsR, TsI, lane, U, V, U128); break;
    }

    int wb = wrp * 16;
    #pragma unroll
    for (int j = 0; j < 16; j++) {
        int w = wb + j;
        Os[lane * 257 + w] = U[j] - V[j];
        if (w) Os[lane * 257 + 256 - w] = U[j] + V[j];
    }
    if (wrp == 0) Os[lane * 257 + 128] = U128;
    __syncthreads();

    float* op = out + (size_t)bo * 65536 + (size_t)h0 * 256;
    for (int i = threadIdx.x; i < 8192; i += 256) {
        int h = i >> 8, w = i & 255;
        op[h * 256 + w] = Os[h * 257 + w];
    }
}

// ---------------------------------------------------------------------------
extern "C" void kernel_launch(void* const* d_in, const int* in_sizes, int n_in,
                              void* d_out, int out_size) {
    (void)in_sizes; (void)n_in; (void)out_size;
    const float* x  = (const float*)d_in[0];
    const float* wr = (const float*)d_in[1];
    const float* wi = (const float*)d_in[2];
    float* out = (float*)d_out;

    k_fwdW<<<dim3(1024, 8), 256>>>(x);
    k_fwdH<<<1024, 256>>>();
    k_mix <<<1024, 256>>>(wr, wi);
    k_invH<<<1024, 256>>>();
    k_invW<<<dim3(1024, 8), 256>>>(out);
}

// round 7
// speedup vs baseline: 1.0102x; 1.0102x over previous
#include <cuda_runtime.h>

// Scratch (no allocation allowed -> __device__ globals)
__device__ float2 g_A[16*64*256*32];   // [bc][h][ky]      67 MB
__device__ float2 g_X[16*32*32*64];    // [b][mode][c]     8.4 MB
__device__ float2 g_M[16*64*32*32];    // [bo][kx][ky]     8.4 MB
__device__ float2 g_T[16*64*256*32];   // [bo][h][ky]      67 MB

// Compile-time twiddles: cos/sin(2*pi*k/256) as exact fp32 literals so ptxas
// can emit FFMA with an immediate multiplier (rt_SMSP=1 vs 2 for 3-reg form).
__host__ __device__ constexpr float TWC(int k) {
    k &= 255;
    if (k > 128) k = 256 - k;               // cos symmetry
    double x = 6.283185307179586476925286766559 * (double)k / 256.0;
    double x2 = x * x, t = 1.0, s = 1.0;
    for (int i = 1; i <= 24; i++) { t *= -x2 / ((2.0*i - 1.0) * (2.0*i)); s += t; }
    return (float)s;
}
__host__ __device__ constexpr float TWS(int k) { return TWC(k - 64); }   // sin

// Device-safe compile-time unroll (no std::integral_constant operator int)
template<int I> struct ic { static constexpr int v = I; };
template<class F, int... Is>
__device__ __forceinline__ void unroll_(F&& f, ic<Is>...) { (f(ic<Is>{}), ...); }
template<int N, class F, int... Is>
__device__ __forceinline__ void unroll_build(F&& f, ic<Is>... tags) {
    if constexpr (sizeof...(Is) == N) { (f(tags), ...); }
    else unroll_build<N>(static_cast<F&&>(f), tags..., ic<sizeof...(Is)>{});
}
// Simpler: recursive unroll
template<int I, int N, class F>
__device__ __forceinline__ void unroll_rec(F&& f) {
    if constexpr (I < N) { f(ic<I>{}); unroll_rec<I + 1, N>(static_cast<F&&>(f)); }
}
template<int N, class F>
__device__ __forceinline__ void unroll(F&& f) { unroll_rec<0, N>(static_cast<F&&>(f)); }

// ---------------------------------------------------------------------------
// K1: forward W-transform, hermitian input fold, imm twiddles.
//   A[h,ky] = (1/256)[ x0 + sum_{p=1..128} xp[p] c(ky p) - i xm[p] s(ky p) ]
// block 256 = 8 warps x 4 ky (template); lane = h. grid (1024 bc, 8 h-tiles).
// ---------------------------------------------------------------------------
template<int KY0>
__device__ __forceinline__ void k1_body(const float* __restrict__ sp,
                                        const float* __restrict__ sm,
                                        int lane, float ar[4], float ai[4]) {
    unroll<128>([&](auto pc) {
        constexpr int P = decltype(pc)::v + 1;
        float xp = sp[(P - 1) * 33 + lane];
        float xm = sm[(P - 1) * 33 + lane];
        unroll<4>([&](auto kc) {
            constexpr int KI = decltype(kc)::v;
            constexpr int KY = KY0 + KI;
            constexpr float C = TWC(KY * P);
            constexpr float S = -TWS(KY * P);
            ar[KI] = fmaf(xp, C, ar[KI]);
            ai[KI] = fmaf(xm, S, ai[KI]);
        });
    });
}

__global__ __launch_bounds__(256) void k_fwdW(const float* __restrict__ x) {
    __shared__ float sp[128 * 33], sm[128 * 33], sx0[32];
    int bc = blockIdx.x, h0 = blockIdx.y * 32;
    const float* xr = x + (size_t)bc * 65536 + (size_t)h0 * 256;

    for (int i = threadIdx.x; i < 4096; i += 256) {
        int f = i & 127, h = i >> 7;
        float a = xr[h * 256 + f + 1];
        float b = xr[h * 256 + 255 - f];
        sp[f * 33 + h] = (f == 127) ? a   : a + b;
        sm[f * 33 + h] = (f == 127) ? 0.f : a - b;
    }
    if (threadIdx.x < 32) sx0[threadIdx.x] = xr[threadIdx.x * 256];
    __syncthreads();

    int lane = threadIdx.x & 31, wrp = threadIdx.x >> 5;
    float x0 = sx0[lane];
    float ar[4], ai[4];
    #pragma unroll
    for (int k = 0; k < 4; k++) { ar[k] = x0; ai[k] = 0.f; }

    switch (wrp) {
        case 0: k1_body<0 >(sp, sm, lane, ar, ai); break;
        case 1: k1_body<4 >(sp, sm, lane, ar, ai); break;
        case 2: k1_body<8 >(sp, sm, lane, ar, ai); break;
        case 3: k1_body<12>(sp, sm, lane, ar, ai); break;
        case 4: k1_body<16>(sp, sm, lane, ar, ai); break;
        case 5: k1_body<20>(sp, sm, lane, ar, ai); break;
        case 6: k1_body<24>(sp, sm, lane, ar, ai); break;
        default:k1_body<28>(sp, sm, lane, ar, ai); break;
    }

    const float sc = 1.0f / 256.0f;   // ortho forward
    float2* A = &g_A[(size_t)bc * 8192];
    #pragma unroll
    for (int k = 0; k < 4; k++)
        A[(h0 + lane) * 32 + wrp * 4 + k] = make_float2(ar[k] * sc, ai[k] * sc);
}

// ---------------------------------------------------------------------------
// K2: forward H-transform, h-parity fold (P = A[h]+A[h+128], Q = A[h]-A[h+128]):
//   X[kx] = sum_{h<128} D[h] e^{-2pi i kx h/256},  D = P if kx even else Q.
// block 256 = 8 warps x 4 kx (template); lane = ky. grid 1024 bc.
// ---------------------------------------------------------------------------
template<int KX0>
__device__ __forceinline__ void k2_body(const float2* __restrict__ sP,
                                        const float2* __restrict__ sQ,
                                        int lane, float xre[4], float xim[4]) {
    unroll<128>([&](auto hc) {
        constexpr int H = decltype(hc)::v;
        float2 p = sP[H * 32 + lane];
        float2 q = sQ[H * 32 + lane];
        unroll<4>([&](auto kc) {
            constexpr int KI = decltype(kc)::v;
            constexpr int KX = KX0 + KI;
            constexpr float C = TWC(KX * H);
            constexpr float S = TWS(KX * H);
            float dr = (KX & 1) ? q.x : p.x;
            float di = (KX & 1) ? q.y : p.y;
            // (dr + i di)(C - i S)
            xre[KI] = fmaf(dr, C, fmaf(di,  S, xre[KI]));
            xim[KI] = fmaf(di, C, fmaf(dr, -S, xim[KI]));
        });
    });
}

__global__ __launch_bounds__(256, 2) void k_fwdH() {
    __shared__ float2 sP[128 * 32], sQ[128 * 32];   // 64 KB
    int bc = blockIdx.x;
    const float2* A = &g_A[(size_t)bc * 8192];

    for (int i = threadIdx.x; i < 4096; i += 256) {
        int ky = i & 31, h = i >> 5;
        float2 a = A[h * 32 + ky];
        float2 b = A[(h + 128) * 32 + ky];
        sP[h * 32 + ky] = make_float2(a.x + b.x, a.y + b.y);
        sQ[h * 32 + ky] = make_float2(a.x - b.x, a.y - b.y);
    }
    __syncthreads();

    int lane = threadIdx.x & 31, wrp = threadIdx.x >> 5;
    float xre[4] = {0,0,0,0}, xim[4] = {0,0,0,0};
    switch (wrp) {
        case 0: k2_body<0 >(sP, sQ, lane, xre, xim); break;
        case 1: k2_body<4 >(sP, sQ, lane, xre, xim); break;
        case 2: k2_body<8 >(sP, sQ, lane, xre, xim); break;
        case 3: k2_body<12>(sP, sQ, lane, xre, xim); break;
        case 4: k2_body<16>(sP, sQ, lane, xre, xim); break;
        case 5: k2_body<20>(sP, sQ, lane, xre, xim); break;
        case 6: k2_body<24>(sP, sQ, lane, xre, xim); break;
        default:k2_body<28>(sP, sQ, lane, xre, xim); break;
    }

    int b = bc >> 6, c = bc & 63;
    #pragma unroll
    for (int k = 0; k < 4; k++)
        g_X[((size_t)b * 1024 + (wrp * 4 + k) * 32 + lane) * 64 + c] =
            make_float2(xre[k], xim[k]);
}

// ---------------------------------------------------------------------------
// K3: channel mix.  M[b,o,m] = sum_c X[b,c,m] * (Wr + i Wi)[c,o,m]
// ---------------------------------------------------------------------------
__global__ __launch_bounds__(256) void k_mix(const float* __restrict__ wr,
                                             const float* __restrict__ wi) {
    int m = blockIdx.x;
    __shared__ float2 Ws[64 * 64];
    __shared__ float2 Xs[16 * 64];

    for (int i = threadIdx.x; i < 4096; i += 256)
        Ws[i] = make_float2(wr[(size_t)i * 1024 + m], wi[(size_t)i * 1024 + m]);
    for (int i = threadIdx.x; i < 1024; i += 256) {
        int b = i >> 6, c = i & 63;
        Xs[i] = g_X[((size_t)b * 1024 + m) * 64 + c];
    }
    __syncthreads();

    #pragma unroll
    for (int k = 0; k < 4; k++) {
        int idx = threadIdx.x + k * 256;
        int b = idx >> 6, o = idx & 63;
        float accr = 0.f, acci = 0.f;
        #pragma unroll 8
        for (int c = 0; c < 64; c++) {
            float2 X  = Xs[b * 64 + c];
            float2 Wv = Ws[c * 64 + o];
            accr = fmaf(X.x, Wv.x, fmaf(-X.y, Wv.y, accr));
            acci = fmaf(X.x, Wv.y, fmaf( X.y, Wv.x, acci));
        }
        g_M[((size_t)b * 64 + o) * 1024 + m] = make_float2(accr, acci);
    }
}

// ---------------------------------------------------------------------------
// K4: inverse H-transform, kx-parity fold (E even kx, Q odd kx):
//   T[h] = (E+Q)*s,  T[h+128] = (E-Q)*s,  s = (ky==0?1:2)/256.
// block 256 = 8 warps x 16 h (template); lane = ky. grid 1024 bo.
// ---------------------------------------------------------------------------
template<int H0>
__device__ __forceinline__ void k4_body(const float2* __restrict__ Ms, int lane,
                                        float Er[16], float Ei[16],
                                        float Qr[16], float Qi[16]) {
    unroll<32>([&](auto xc) {
        constexpr int KX = decltype(xc)::v;
        float2 m = Ms[KX * 32 + lane];
        unroll<16>([&](auto hc) {
            constexpr int HI = decltype(hc)::v;
            constexpr int H = H0 + HI;
            constexpr float C = TWC(KX * H);
            constexpr float S = TWS(KX * H);
            // (Mr + i Mi)(C + i S)
            if constexpr (KX & 1) {
                Qr[HI] = fmaf(m.x, C, fmaf(m.y, -S, Qr[HI]));
                Qi[HI] = fmaf(m.x, S, fmaf(m.y,  C, Qi[HI]));
            } else {
                Er[HI] = fmaf(m.x, C, fmaf(m.y, -S, Er[HI]));
                Ei[HI] = fmaf(m.x, S, fmaf(m.y,  C, Ei[HI]));
            }
        });
    });
}

__global__ __launch_bounds__(256, 2) void k_invH() {
    __shared__ float2 Ms[1024];
    int bo = blockIdx.x;
    for (int i = threadIdx.x; i < 1024; i += 256)
        Ms[i] = g_M[(size_t)bo * 1024 + i];
    __syncthreads();

    int lane = threadIdx.x & 31, wrp = threadIdx.x >> 5;
    float Er[16] = {}, Ei[16] = {}, Qr[16] = {}, Qi[16] = {};
    switch (wrp) {
        case 0: k4_body<0  >(Ms, lane, Er, Ei, Qr, Qi); break;
        case 1: k4_body<16 >(Ms, lane, Er, Ei, Qr, Qi); break;
        case 2: k4_body<32 >(Ms, lane, Er, Ei, Qr, Qi); break;
        case 3: k4_body<48 >(Ms, lane, Er, Ei, Qr, Qi); break;
        case 4: k4_body<64 >(Ms, lane, Er, Ei, Qr, Qi); break;
        case 5: k4_body<80 >(Ms, lane, Er, Ei, Qr, Qi); break;
        case 6: k4_body<96 >(Ms, lane, Er, Ei, Qr, Qi); break;
        default:k4_body<112>(Ms, lane, Er, Ei, Qr, Qi); break;
    }

    float s = (lane == 0 ? 1.0f : 2.0f) * (1.0f / 256.0f);
    float2* T = &g_T[(size_t)bo * 8192];
    int hb = wrp * 16;
    #pragma unroll
    for (int j = 0; j < 16; j++) {
        int h = hb + j;
        T[h * 32 + lane]         = make_float2((Er[j] + Qr[j]) * s, (Ei[j] + Qi[j]) * s);
        T[(h + 128) * 32 + lane] = make_float2((Er[j] - Qr[j]) * s, (Ei[j] - Qi[j]) * s);
    }
}

// ---------------------------------------------------------------------------
// K5: inverse W-transform, output fold over (w, 256-w):
//   U = sum_ky TR c(ky w), V = sum_ky TI s(ky w); out[w]=U-V, out[256-w]=U+V;
//   out[128] = sum_ky TR (-1)^ky  (warp 0 extra accumulator).
// block 256 = 8 warps x 16 w (template); lane = h. grid (1024 bo, 8 h-tiles).
// ---------------------------------------------------------------------------
template<int W0>
__device__ __forceinline__ void k5_body(const float* __restrict__ TsR,
                                        const float* __restrict__ TsI,
                                        int lane, float U[16], float V[16],
                                        float& U128) {
    unroll<32>([&](auto yc) {
        constexpr int KY = decltype(yc)::v;
        float tr = TsR[lane * 33 + KY];
        float ti = TsI[lane * 33 + KY];
        unroll<16>([&](auto wc) {
            constexpr int WI = decltype(wc)::v;
            constexpr int W = W0 + WI;
            constexpr float C = TWC(KY * W);
            constexpr float S = TWS(KY * W);
            U[WI] = fmaf(tr, C, U[WI]);
            V[WI] = fmaf(ti, S, V[WI]);
        });
        if constexpr (W0 == 0) {
            constexpr float C128 = TWC(128 * KY);
            U128 = fmaf(tr, C128, U128);
        }
    });
}

__global__ __launch_bounds__(256) void k_invW(float* __restrict__ out) {
    __shared__ float TsR[32 * 33], TsI[32 * 33];
    __shared__ float Os[32 * 257];
    int bo = blockIdx.x, h0 = blockIdx.y * 32;

    const float2* T = &g_T[((size_t)bo * 256 + h0) * 32];
    for (int i = threadIdx.x; i < 1024; i += 256) {
        int ky = i & 31, h = i >> 5;
        float2 t = T[h * 32 + ky];
        TsR[h * 33 + ky] = t.x;
        TsI[h * 33 + ky] = t.y;
    }
    __syncthreads();

    int lane = threadIdx.x & 31, wrp = threadIdx.x >> 5;
    float U[16] = {}, V[16] = {}, U128 = 0.f;
    switch (wrp) {
        case 0: k5_body<0  >(TsR, TsI, lane, U, V, U128); break;
        case 1: k5_body<16 >(TsR, TsI, lane, U, V, U128); break;
        case 2: k5_body<32 >(TsR, TsI, lane, U, V, U128); break;
        case 3: k5_body<48 >(TsR, TsI, lane, U, V, U128); break;
        case 4: k5_body<64 >(TsR, TsI, lane, U, V, U128); break;
        case 5: k5_body<80 >(TsR, TsI, lane, U, V, U128); break;
        case 6: k5_body<96 >(TsR, TsI, lane, U, V, U128); break;
        default:k5_body<112>(TsR, TsI, lane, U, V, U128); break;
    }

    int wb = wrp * 16;
    #pragma unroll
    for (int j = 0; j < 16; j++) {
        int w = wb + j;
        Os[lane * 257 + w] = U[j] - V[j];
        if (w) Os[lane * 257 + 256 - w] = U[j] + V[j];
    }
    if (wrp == 0) Os[lane * 257 + 128] = U128;
    __syncthreads();

    float* op = out + (size_t)bo * 65536 + (size_t)h0 * 256;
    for (int i = threadIdx.x; i < 8192; i += 256) {
        int h = i >> 8, w = i & 255;
        op[h * 256 + w] = Os[h * 257 + w];
    }
}

// ---------------------------------------------------------------------------
extern "C" void kernel_launch(void* const* d_in, const int* in_sizes, int n_in,
                              void* d_out, int out_size) {
    (void)in_sizes; (void)n_in; (void)out_size;
    const float* x  = (const float*)d_in[0];
    const float* wr = (const float*)d_in[1];
    const float* wi = (const float*)d_in[2];
    float* out = (float*)d_out;

    k_fwdW<<<dim3(1024, 8), 256>>>(x);
    k_fwdH<<<1024, 256>>>();
    k_mix <<<1024, 256>>>(wr, wi);
    k_invH<<<1024, 256>>>();
    k_invW<<<dim3(1024, 8), 256>>>(out);
}

// round 8
// speedup vs baseline: 1.3466x; 1.3329x over previous
#include <cuda_runtime.h>
typedef unsigned long long ULL;

__device__ float2 g_A[16*64*256*32];   // [bc][h][ky]
__device__ float2 g_X[16*32*32*64];    // [b][mode][c]
__device__ float2 g_M[16*64*32*32];    // [bo][kx][ky]
__device__ float2 g_T[16*64*256*32];   // [bo][h][ky]
__device__ ULL        g_t1[256];       // (cos, -sin)
__device__ ulonglong2 g_t2[256];       // ((c,c),(s,-s))
__device__ ulonglong2 g_t4[256];       // ((c,s),(-s,c))
__device__ ULL        g_t5[256];       // (c, s)

__device__ __forceinline__ ULL ff2(ULL a, ULL b, ULL c) {
    ULL d; asm("fma.rn.f32x2 %0, %1, %2, %3;" : "=l"(d) : "l"(a), "l"(b), "l"(c)); return d;
}
__device__ __forceinline__ ULL add2(ULL a, ULL b) {
    ULL d; asm("add.rn.f32x2 %0, %1, %2;" : "=l"(d) : "l"(a), "l"(b)); return d;
}
__device__ __forceinline__ ULL sub2(ULL a, ULL b) {
    ULL d; asm("sub.rn.f32x2 %0, %1, %2;" : "=l"(d) : "l"(a), "l"(b)); return d;
}
__device__ __forceinline__ ULL mul2(ULL a, ULL b) {
    ULL d; asm("mul.rn.f32x2 %0, %1, %2;" : "=l"(d) : "l"(a), "l"(b)); return d;
}
__device__ __forceinline__ ULL pack2(float x, float y) {
    ULL d; asm("mov.b64 %0, {%1, %2};" : "=l"(d) : "f"(x), "f"(y)); return d;
}
__device__ __forceinline__ float2 unpack2(ULL v) {
    float2 r; asm("mov.b64 {%0, %1}, %2;" : "=f"(r.x), "=f"(r.y) : "l"(v)); return r;
}

__global__ void k_tw() {
    int k = threadIdx.x;            // 256 threads
    double a = 6.283185307179586476925286766559 * k / 256.0;
    float c = (float)cos(a), s = (float)sin(a);
    g_t1[k] = pack2(c, -s);
    g_t2[k] = make_ulonglong2(pack2(c, c), pack2(s, -s));
    g_t4[k] = make_ulonglong2(pack2(c, s), pack2(-s, c));
    g_t5[k] = pack2(c, s);
}

// ---------------------------------------------------------------------------
// K1: A[h,ky] = (1/256)[x0 + sum_p (xp,xm)*(c,-s)(ky p)] ; grid 1024, blk 256
// lane=h(32), 8 warps x 4 ky, thread 8 h (lane+32j). p staged in 4 chunks.
// ---------------------------------------------------------------------------
__global__ __launch_bounds__(256) void k_fwdW(const float* __restrict__ x) {
    __shared__ ULL sd[32 * 258];      // chunk data / output staging
    __shared__ ULL st1[256];
    int bc = blockIdx.x;
    const float* xr = x + (size_t)bc * 65536;
    if (threadIdx.x < 256) st1[threadIdx.x] = g_t1[threadIdx.x];

    int lane = threadIdx.x & 31, wrp = threadIdx.x >> 5, ky0 = wrp * 4;
    ULL acc[4][8];
    #pragma unroll
    for (int j = 0; j < 8; j++) {
        float x0 = xr[(lane + 32 * j) * 256];
        #pragma unroll
        for (int k = 0; k < 4; k++) acc[k][j] = pack2(x0, 0.f);
    }
    int idx[4];
    #pragma unroll
    for (int k = 0; k < 4; k++) idx[k] = ky0 + k;   // idx = ky*p at p=1

    for (int pc = 0; pc < 4; pc++) {
        __syncthreads();
        for (int i = threadIdx.x; i < 8192; i += 256) {
            int h = i >> 5, j = i & 31, p = pc * 32 + j + 1;
            float a = xr[h * 256 + p];
            if (p == 128) sd[j * 258 + h] = pack2(a, 0.f);
            else {
                float b = xr[h * 256 + 256 - p];
                sd[j * 258 + h] = pack2(a + b, a - b);
            }
        }
        __syncthreads();
        #pragma unroll 8
        for (int pl = 0; pl < 32; pl++) {
            ULL d[8];
            #pragma unroll
            for (int j = 0; j < 8; j++) d[j] = sd[pl * 258 + lane + 32 * j];
            #pragma unroll
            for (int k = 0; k < 4; k++) {
                ULL t = st1[idx[k]];
                #pragma unroll
                for (int j = 0; j < 8; j++) acc[k][j] = ff2(d[j], t, acc[k][j]);
                idx[k] = (idx[k] + ky0 + k) & 255;
            }
        }
    }

    __syncthreads();
    ULL sc = pack2(1.f / 256.f, 1.f / 256.f);
    #pragma unroll
    for (int k = 0; k < 4; k++)
        #pragma unroll
        for (int j = 0; j < 8; j++)
            sd[(ky0 + k) * 258 + lane + 32 * j] = mul2(acc[k][j], sc);  // [ky][h]
    __syncthreads();
    ULL* A = reinterpret_cast<ULL*>(&g_A[(size_t)bc * 8192]);
    for (int i = threadIdx.x; i < 8192; i += 256)
        A[i] = sd[(i & 31) * 258 + (i >> 5)];       // out [h][ky]
}

// ---------------------------------------------------------------------------
// K2: X[kx,ky] = sum_{h<128} D[h]*(c-is)(kx h), D = P(even kx)/Q(odd kx).
// grid 1024, blk 256; lane=ky; warp w: parity w&1, kx = par+8*(w>>1)+2t.
// ---------------------------------------------------------------------------
__global__ __launch_bounds__(256) void k_fwdH() {
    __shared__ ULL sP[128 * 32], sQ[128 * 32];
    __shared__ ulonglong2 st2[256];
    int bc = blockIdx.x;
    const ULL* A = reinterpret_cast<const ULL*>(&g_A[(size_t)bc * 8192]);
    if (threadIdx.x < 256) st2[threadIdx.x] = g_t2[threadIdx.x];
    for (int i = threadIdx.x; i < 4096; i += 256) {
        ULL a = A[i], b = A[i + 4096];
        sP[i] = add2(a, b); sQ[i] = sub2(a, b);
    }
    __syncthreads();

    int lane = threadIdx.x & 31, wrp = threadIdx.x >> 5;
    int par = wrp & 1, base = par + 8 * (wrp >> 1);
    const ULL* sD = par ? sQ : sP;
    ULL acc[4]; int idx[4]; int kxv[4];
    #pragma unroll
    for (int t = 0; t < 4; t++) { acc[t] = 0; idx[t] = 0; kxv[t] = base + 2 * t; }

    #pragma unroll 4
    for (int h = 0; h < 128; h++) {
        ULL d = sD[h * 32 + lane];
        float2 f = unpack2(d);
        ULL dsn = pack2(f.y, f.x);
        #pragma unroll
        for (int t = 0; t < 4; t++) {
            ulonglong2 tw = st2[idx[t]];
            acc[t] = ff2(d, tw.x, ff2(dsn, tw.y, acc[t]));
            idx[t] = (idx[t] + kxv[t]) & 255;
        }
    }
    int b = bc >> 6, c = bc & 63;
    #pragma unroll
    for (int t = 0; t < 4; t++) {
        float2 f = unpack2(acc[t]);
        g_X[((size_t)b * 1024 + kxv[t] * 32 + lane) * 64 + c] = f;
    }
}

// ---------------------------------------------------------------------------
// K3: channel mix (unchanged).
// ---------------------------------------------------------------------------
__global__ __launch_bounds__(256) void k_mix(const float* __restrict__ wr,
                                             const float* __restrict__ wi) {
    int m = blockIdx.x;
    __shared__ float2 Ws[4096], Xs[1024];
    for (int i = threadIdx.x; i < 4096; i += 256)
        Ws[i] = make_float2(wr[(size_t)i * 1024 + m], wi[(size_t)i * 1024 + m]);
    for (int i = threadIdx.x; i < 1024; i += 256)
        Xs[i] = g_X[((size_t)(i >> 6) * 1024 + m) * 64 + (i & 63)];
    __syncthreads();
    #pragma unroll
    for (int k = 0; k < 4; k++) {
        int id = threadIdx.x + k * 256, b = id >> 6, o = id & 63;
        float ar = 0.f, ai = 0.f;
        #pragma unroll 8
        for (int c = 0; c < 64; c++) {
            float2 X = Xs[b * 64 + c], W = Ws[c * 64 + o];
            ar = fmaf(X.x, W.x, fmaf(-X.y, W.y, ar));
            ai = fmaf(X.x, W.y, fmaf( X.y, W.x, ai));
        }
        g_M[((size_t)b * 64 + o) * 1024 + m] = make_float2(ar, ai);
    }
}

// ---------------------------------------------------------------------------
// K4: T[h]=(E+O)s, T[h+128]=(E-O)s over kx parity. grid 1024, blk 256.
// lane=ky; warp w: h = w*16+j (j<16).
// ---------------------------------------------------------------------------
__global__ __launch_bounds__(256) void k_invH() {
    __shared__ ULL Ms[1024];
    __shared__ ulonglong2 st4[256];
    int bo = blockIdx.x;
    const ULL* M = reinterpret_cast<const ULL*>(&g_M[(size_t)bo * 1024]);
    if (threadIdx.x < 256) st4[threadIdx.x] = g_t4[threadIdx.x];
    for (int i = threadIdx.x; i < 1024; i += 256) Ms[i] = M[i];
    __syncthreads();

    int lane = threadIdx.x & 31, wrp = threadIdx.x >> 5, hb = wrp * 16;
    ULL E[16], O[16]; int idx[16];
    #pragma unroll
    for (int j = 0; j < 16; j++) { E[j] = 0; O[j] = 0; idx[j] = 0; }

    #pragma unroll
    for (int kx = 0; kx < 32; kx++) {
        float2 f = unpack2(Ms[kx * 32 + lane]);
        ULL mrr = pack2(f.x, f.x), mii = pack2(f.y, f.y);
        #pragma unroll
        for (int j = 0; j < 16; j++) {
            ulonglong2 tw = st4[idx[j]];
            if (kx & 1) O[j] = ff2(mrr, tw.x, ff2(mii, tw.y, O[j]));
            else        E[j] = ff2(mrr, tw.x, ff2(mii, tw.y, E[j]));
            idx[j] = (idx[j] + hb + j) & 255;
        }
    }
    float sv = (lane == 0 ? 1.f : 2.f) / 256.f;
    ULL s2 = pack2(sv, sv);
    ULL* T = reinterpret_cast<ULL*>(&g_T[(size_t)bo * 8192]);
    #pragma unroll
    for (int j = 0; j < 16; j++) {
        T[(hb + j) * 32 + lane]       = mul2(add2(E[j], O[j]), s2);
        T[(hb + j + 128) * 32 + lane] = mul2(sub2(E[j], O[j]), s2);
    }
}

// ---------------------------------------------------------------------------
// K5: (U,V) += (TR,TI)*(c,s)(ky w); out[w]=U-V, out[256-w]=U+V, out[128]=U128.
// grid (1024,4): 64-h tiles; blk 256; lane=h (2 per thread), 8 warps x 16 w.
// ---------------------------------------------------------------------------
__global__ __launch_bounds__(256) void k_invW(float* __restrict__ out) {
    __shared__ ULL Ts[64 * 33];
    __shared__ ULL st5[256];
    __shared__ float Os[64 * 257];
    int bo = blockIdx.x, h0 = blockIdx.y * 64;
    const ULL* T = reinterpret_cast<const ULL*>(&g_T[((size_t)bo * 256 + h0) * 32]);
    if (threadIdx.x < 256) st5[threadIdx.x] = g_t5[threadIdx.x];
    for (int i = threadIdx.x; i < 2048; i += 256)
        Ts[(i >> 5) * 33 + (i & 31)] = T[i];
    __syncthreads();

    int lane = threadIdx.x & 31, wrp = threadIdx.x >> 5, wb = wrp * 16;
    ULL acc[2][16]; int idx[16]; ULL u128[2] = {0, 0}; int idx128 = 0;
    #pragma unroll
    for (int j = 0; j < 16; j++) { acc[0][j] = 0; acc[1][j] = 0; idx[j] = 0; }

    #pragma unroll 4
    for (int ky = 0; ky < 32; ky++) {
        ULL d0 = Ts[lane * 33 + ky], d1 = Ts[(lane + 32) * 33 + ky];
        #pragma unroll
        for (int j = 0; j < 16; j++) {
            ULL t = st5[idx[j]];
            acc[0][j] = ff2(d0, t, acc[0][j]);
            acc[1][j] = ff2(d1, t, acc[1][j]);
            idx[j] = (idx[j] + wb + j) & 255;
        }
        if (wrp == 0) {
            ULL t = st5[idx128];
            u128[0] = ff2(d0, t, u128[0]);
            u128[1] = ff2(d1, t, u128[1]);
            idx128 = (idx128 + 128) & 255;
        }
    }
    #pragma unroll
    for (int g = 0; g < 2; g++) {
        int hl = lane + 32 * g;
        #pragma unroll
        for (int j = 0; j < 16; j++) {
            int w = wb + j;
            float2 f = unpack2(acc[g][j]);
            Os[hl * 257 + w] = f.x - f.y;
            if (w) Os[hl * 257 + 256 - w] = f.x + f.y;
        }
        if (wrp == 0) Os[hl * 257 + 128] = unpack2(u128[g]).x;
    }
    __syncthreads();
    float* op = out + (size_t)bo * 65536 + (size_t)h0 * 256;
    for (int i = threadIdx.x; i < 16384; i += 256)
        op[i] = Os[(i >> 8) * 257 + (i & 255)];
}

// ---------------------------------------------------------------------------
extern "C" void kernel_launch(void* const* d_in, const int* in_sizes, int n_in,
                              void* d_out, int out_size) {
    (void)in_sizes; (void)n_in; (void)out_size;
    const float* x  = (const float*)d_in[0];
    const float* wr = (const float*)d_in[1];
    const float* wi = (const float*)d_in[2];
    float* out = (float*)d_out;

    k_tw  <<<1, 256>>>();
    k_fwdW<<<1024, 256>>>(x);
    k_fwdH<<<1024, 256>>>();
    k_mix <<<1024, 256>>>(wr, wi);
    k_invH<<<1024, 256>>>();
    k_invW<<<dim3(1024, 4), 256>>>(out);
}

// round 10
// speedup vs baseline: 1.5349x; 1.1399x over previous
#include <cuda_runtime.h>
#include <cuda_bf16.h>
#include <cstdint>
typedef unsigned long long ULL;

__device__ float2 g_A[16*64*256*32];   // [bc][h][ky]
__device__ float2 g_X[16*32*32*64];    // [b][mode][c]
__device__ float2 g_M[16*64*32*32];    // [bo][kx][ky]
__device__ float2 g_T[16*64*256*32];   // [bo][h][ky]
__device__ float2 g_Wt[1024*64*64];    // [m][c][o]
__device__ ULL        g_t1[256];       // (cos, -sin)
__device__ ulonglong2 g_t2[256];       // ((c,c),(s,-s))
__device__ ulonglong2 g_t4[256];       // ((c,s),(-s,c))
__device__ __nv_bfloat16 g_B5h[256*64], g_B5l[256*64];  // [w][k] k<32:cos, k>=32:-sin

__device__ __forceinline__ ULL ff2(ULL a, ULL b, ULL c) {
    ULL d; asm("fma.rn.f32x2 %0, %1, %2, %3;" : "=l"(d) : "l"(a), "l"(b), "l"(c)); return d;
}
__device__ __forceinline__ ULL add2(ULL a, ULL b) {
    ULL d; asm("add.rn.f32x2 %0, %1, %2;" : "=l"(d) : "l"(a), "l"(b)); return d;
}
__device__ __forceinline__ ULL sub2(ULL a, ULL b) {
    ULL d; asm("sub.rn.f32x2 %0, %1, %2;" : "=l"(d) : "l"(a), "l"(b)); return d;
}
__device__ __forceinline__ ULL mul2(ULL a, ULL b) {
    ULL d; asm("mul.rn.f32x2 %0, %1, %2;" : "=l"(d) : "l"(a), "l"(b)); return d;
}
__device__ __forceinline__ ULL pack2(float x, float y) {
    ULL d; asm("mov.b64 %0, {%1, %2};" : "=l"(d) : "f"(x), "f"(y)); return d;
}
__device__ __forceinline__ float2 unpack2(ULL v) {
    float2 r; asm("mov.b64 {%0, %1}, %2;" : "=f"(r.x), "=f"(r.y) : "l"(v)); return r;
}

__global__ void k_tw() {
    int k = threadIdx.x;
    double a = 6.283185307179586476925286766559 * k / 256.0;
    float c = (float)cos(a), s = (float)sin(a);
    g_t1[k] = pack2(c, -s);
    g_t2[k] = make_ulonglong2(pack2(c, c), pack2(s, -s));
    g_t4[k] = make_ulonglong2(pack2(c, s), pack2(-s, c));
}
__global__ void k_tw2() {           // grid 256 (w), 64 thr (k)
    int w = blockIdx.x, k = threadIdx.x;
    double a = 6.283185307179586476925286766559 * ((k & 31) * w) / 256.0;
    float v = (k < 32) ? (float)cos(a) : -(float)sin(a);
    __nv_bfloat16 hi = __float2bfloat16(v);
    g_B5h[w * 64 + k] = hi;
    g_B5l[w * 64 + k] = __float2bfloat16(v - __bfloat162float(hi));
}

// Weight transpose: [c][o][m] -> g_Wt[m][c][o]. grid (128 co-tiles, 32 m-tiles).
__global__ __launch_bounds__(256) void k_wt(const float* __restrict__ wr,
                                            const float* __restrict__ wi) {
    __shared__ float2 st[32][33];
    int co0 = blockIdx.x * 32, m0 = blockIdx.y * 32;
    for (int i = threadIdx.x; i < 1024; i += 256) {
        int lco = i >> 5, lm = i & 31;
        size_t src = (size_t)(co0 + lco) * 1024 + m0 + lm;
        st[lco][lm] = make_float2(wr[src], wi[src]);
    }
    __syncthreads();
    for (int i = threadIdx.x; i < 1024; i += 256) {
        int lm = i >> 5, lco = i & 31;
        g_Wt[(size_t)(m0 + lm) * 4096 + co0 + lco] = st[lco][lm];
    }
}

// K1: fwd W-transform, hermitian fold, FFMA2 + table.
__global__ __launch_bounds__(256) void k_fwdW(const float* __restrict__ x) {
    __shared__ ULL sd[32 * 258];
    __shared__ ULL st1[256];
    int bc = blockIdx.x;
    const float* xr = x + (size_t)bc * 65536;
    if (threadIdx.x < 256) st1[threadIdx.x] = g_t1[threadIdx.x];

    int lane = threadIdx.x & 31, wrp = threadIdx.x >> 5, ky0 = wrp * 4;
    ULL acc[4][8];
    #pragma unroll
    for (int j = 0; j < 8; j++) {
        float x0 = xr[(lane + 32 * j) * 256];
        #pragma unroll
        for (int k = 0; k < 4; k++) acc[k][j] = pack2(x0, 0.f);
    }
    int idx[4];
    #pragma unroll
    for (int k = 0; k < 4; k++) idx[k] = ky0 + k;

    for (int pc = 0; pc < 4; pc++) {
        __syncthreads();
        for (int i = threadIdx.x; i < 8192; i += 256) {
            int h = i >> 5, j = i & 31, p = pc * 32 + j + 1;
            float a = xr[h * 256 + p];
            if (p == 128) sd[j * 258 + h] = pack2(a, 0.f);
            else { float b = xr[h * 256 + 256 - p]; sd[j * 258 + h] = pack2(a + b, a - b); }
        }
        __syncthreads();
        #pragma unroll 8
        for (int pl = 0; pl < 32; pl++) {
            ULL d[8];
            #pragma unroll
            for (int j = 0; j < 8; j++) d[j] = sd[pl * 258 + lane + 32 * j];
            #pragma unroll
            for (int k = 0; k < 4; k++) {
                ULL t = st1[idx[k]];
                #pragma unroll
                for (int j = 0; j < 8; j++) acc[k][j] = ff2(d[j], t, acc[k][j]);
                idx[k] = (idx[k] + ky0 + k) & 255;
            }
        }
    }
    __syncthreads();
    ULL sc = pack2(1.f / 256.f, 1.f / 256.f);
    #pragma unroll
    for (int k = 0; k < 4; k++)
        #pragma unroll
        for (int j = 0; j < 8; j++)
            sd[(ky0 + k) * 258 + lane + 32 * j] = mul2(acc[k][j], sc);
    __syncthreads();
    ULL* A = reinterpret_cast<ULL*>(&g_A[(size_t)bc * 8192]);
    for (int i = threadIdx.x; i < 8192; i += 256)
        A[i] = sd[(i & 31) * 258 + (i >> 5)];
}

// K2: fwd H-transform, h-parity fold.
__global__ __launch_bounds__(256) void k_fwdH() {
    __shared__ ULL sP[128 * 32], sQ[128 * 32];
    __shared__ ulonglong2 st2[256];
    int bc = blockIdx.x;
    const ULL* A = reinterpret_cast<const ULL*>(&g_A[(size_t)bc * 8192]);
    if (threadIdx.x < 256) st2[threadIdx.x] = g_t2[threadIdx.x];
    for (int i = threadIdx.x; i < 4096; i += 256) {
        ULL a = A[i], b = A[i + 4096];
        sP[i] = add2(a, b); sQ[i] = sub2(a, b);
    }
    __syncthreads();
    int lane = threadIdx.x & 31, wrp = threadIdx.x >> 5;
    int par = wrp & 1, base = par + 8 * (wrp >> 1);
    const ULL* sD = par ? sQ : sP;
    ULL acc[4]; int idx[4]; int kxv[4];
    #pragma unroll
    for (int t = 0; t < 4; t++) { acc[t] = 0; idx[t] = 0; kxv[t] = base + 2 * t; }
    #pragma unroll 4
    for (int h = 0; h < 128; h++) {
        ULL d = sD[h * 32 + lane];
        float2 f = unpack2(d);
        ULL dsn = pack2(f.y, f.x);
        #pragma unroll
        for (int t = 0; t < 4; t++) {
            ulonglong2 tw = st2[idx[t]];
            acc[t] = ff2(d, tw.x, ff2(dsn, tw.y, acc[t]));
            idx[t] = (idx[t] + kxv[t]) & 255;
        }
    }
    int b = bc >> 6, c = bc & 63;
    #pragma unroll
    for (int t = 0; t < 4; t++)
        g_X[((size_t)b * 1024 + kxv[t] * 32 + lane) * 64 + c] = unpack2(acc[t]);
}

// K3: channel mix, weights coalesced from g_Wt.
__global__ __launch_bounds__(256) void k_mix() {
    int m = blockIdx.x;
    __shared__ float2 Ws[4096], Xs[1024];
    for (int i = threadIdx.x; i < 4096; i += 256)
        Ws[i] = g_Wt[(size_t)m * 4096 + i];
    for (int i = threadIdx.x; i < 1024; i += 256)
        Xs[i] = g_X[((size_t)(i >> 6) * 1024 + m) * 64 + (i & 63)];
    __syncthreads();
    #pragma unroll
    for (int k = 0; k < 4; k++) {
        int id = threadIdx.x + k * 256, b = id >> 6, o = id & 63;
        float ar = 0.f, ai = 0.f;
        #pragma unroll 8
        for (int c = 0; c < 64; c++) {
            float2 X = Xs[b * 64 + c], W = Ws[c * 64 + o];
            ar = fmaf(X.x, W.x, fmaf(-X.y, W.y, ar));
            ai = fmaf(X.x, W.y, fmaf( X.y, W.x, ai));
        }
        g_M[((size_t)b * 64 + o) * 1024 + m] = make_float2(ar, ai);
    }
}

// K4: inv H-transform, kx-parity fold.
__global__ __launch_bounds__(256) void k_invH() {
    __shared__ ULL Ms[1024];
    __shared__ ulonglong2 st4[256];
    int bo = blockIdx.x;
    const ULL* M = reinterpret_cast<const ULL*>(&g_M[(size_t)bo * 1024]);
    if (threadIdx.x < 256) st4[threadIdx.x] = g_t4[threadIdx.x];
    for (int i = threadIdx.x; i < 1024; i += 256) Ms[i] = M[i];
    __syncthreads();
    int lane = threadIdx.x & 31, wrp = threadIdx.x >> 5, hb = wrp * 16;
    ULL E[16], O[16]; int idx[16];
    #pragma unroll
    for (int j = 0; j < 16; j++) { E[j] = 0; O[j] = 0; idx[j] = 0; }
    #pragma unroll
    for (int kx = 0; kx < 32; kx++) {
        float2 f = unpack2(Ms[kx * 32 + lane]);
        ULL mrr = pack2(f.x, f.x), mii = pack2(f.y, f.y);
        #pragma unroll
        for (int j = 0; j < 16; j++) {
            ulonglong2 tw = st4[idx[j]];
            if (kx & 1) O[j] = ff2(mrr, tw.x, ff2(mii, tw.y, O[j]));
            else        E[j] = ff2(mrr, tw.x, ff2(mii, tw.y, E[j]));
            idx[j] = (idx[j] + hb + j) & 255;
        }
    }
    float sv = (lane == 0 ? 1.f : 2.f) / 256.f;
    ULL s2 = pack2(sv, sv);
    ULL* T = reinterpret_cast<ULL*>(&g_T[(size_t)bo * 8192]);
    #pragma unroll
    for (int j = 0; j < 16; j++) {
        T[(hb + j) * 32 + lane]       = mul2(add2(E[j], O[j]), s2);
        T[(hb + j + 128) * 32 + lane] = mul2(sub2(E[j], O[j]), s2);
    }
}

// K5: tensor-core inverse W.  D[64h,128w] = [TR|TI] x [cos;-sin] via bf16 2-split
// (Ahi*Bhi + Ahi*Blo + Alo*Bhi = 12 k16-chunks).  grid (256 bo-grp, 2 w, 4 h).
__global__ __launch_bounds__(256) void k_invW(float* __restrict__ out) {
    __shared__ uint32_t As[2][64][32];   // [split][h][k-b32], XOR-swizzled
    __shared__ uint32_t Bs[2][128][32];  // [split][w][k-b32], XOR-swizzled
    int bog = blockIdx.x, w0 = blockIdx.y * 128, h0 = blockIdx.z * 64;
    int tid = threadIdx.x;

    for (int i = tid; i < 4096; i += 256) {     // stage B once
        int w = i >> 5, cb = i & 31;
        int sc = cb ^ ((w & 7) << 2);
        Bs[0][w][sc] = *reinterpret_cast<const uint32_t*>(&g_B5h[(w0 + w) * 64 + cb * 2]);
        Bs[1][w][sc] = *reinterpret_cast<const uint32_t*>(&g_B5l[(w0 + w) * 64 + cb * 2]);
    }

    int lane = tid & 31, wrp = tid >> 5;
    int gid = lane >> 2, tig = lane & 3;
    int wm = wrp & 1, wn = wrp >> 1;

    for (int s = 0; s < 4; s++) {
        int bo = bog * 4 + s;
        __syncthreads();
        const float2* T = &g_T[((size_t)bo * 256 + h0) * 32];
        __nv_bfloat16* Ab = reinterpret_cast<__nv_bfloat16*>(As);
        for (int i = tid; i < 2048; i += 256) {
            int h = i >> 5, ky = i & 31;
            float2 v = T[i];
            #pragma unroll
            for (int q = 0; q < 2; q++) {
                int k = ky + q * 32;
                float f = q ? v.y : v.x;
                __nv_bfloat16 hi = __float2bfloat16(f);
                __nv_bfloat16 lo = __float2bfloat16(f - __bfloat162float(hi));
                int wd = (k >> 1) ^ ((h & 7) << 2);
                int base = (h * 32 + wd) * 2 + (k & 1);
                Ab[base] = hi;
                Ab[4096 + base] = lo;
            }
        }
        __syncthreads();

        float d[2][4][4];
        #pragma unroll
        for (int mt = 0; mt < 2; mt++)
            #pragma unroll
            for (int nt = 0; nt < 4; nt++)
                { d[mt][nt][0]=0.f; d[mt][nt][1]=0.f; d[mt][nt][2]=0.f; d[mt][nt][3]=0.f; }

        #pragma unroll
        for (int c = 0; c < 12; c++) {
            int asel = (c >= 8) ? 1 : 0;
            int bsel = (c >= 4 && c < 8) ? 1 : 0;
            int kb = (c & 3) * 8;
            uint32_t a[2][4];
            #pragma unroll
            for (int mt = 0; mt < 2; mt++) {
                int r0 = wm * 32 + mt * 16 + gid, r1 = r0 + 8;
                a[mt][0] = As[asel][r0][(kb + tig)     ^ ((r0 & 7) << 2)];
                a[mt][1] = As[asel][r1][(kb + tig)     ^ ((r1 & 7) << 2)];
                a[mt][2] = As[asel][r0][(kb + 4 + tig) ^ ((r0 & 7) << 2)];
                a[mt][3] = As[asel][r1][(kb + 4 + tig) ^ ((r1 & 7) << 2)];
            }
            #pragma unroll
            for (int nt = 0; nt < 4; nt++) {
                int wr_ = wn * 32 + nt * 8 + gid;
                uint32_t b0 = Bs[bsel][wr_][(kb + tig)     ^ ((wr_ & 7) << 2)];
                uint32_t b1 = Bs[bsel][wr_][(kb + 4 + tig) ^ ((wr_ & 7) << 2)];
                #pragma unroll
                for (int mt = 0; mt < 2; mt++) {
                    asm("mma.sync.aligned.m16n8k16.row.col.f32.bf16.bf16.f32 "
                        "{%0,%1,%2,%3}, {%4,%5,%6,%7}, {%8,%9}, {%0,%1,%2,%3};"
                        : "+f"(d[mt][nt][0]), "+f"(d[mt][nt][1]),
                          "+f"(d[mt][nt][2]), "+f"(d[mt][nt][3])
                        : "r"(a[mt][0]), "r"(a[mt][1]), "r"(a[mt][2]), "r"(a[mt][3]),
                          "r"(b0), "r"(b1));
                }
            }
        }
        float* op = out + (size_t)bo * 65536 + (size_t)h0 * 256 + w0;
        #pragma unroll
        for (int mt = 0; mt < 2; mt++) {
            int r0 = wm * 32 + mt * 16 + gid;
            #pragma unroll
            for (int nt = 0; nt < 4; nt++) {
                int cc = wn * 32 + nt * 8 + tig * 2;
                *reinterpret_cast<float2*>(op + (size_t)r0 * 256 + cc) =
                    make_float2(d[mt][nt][0], d[mt][nt][1]);
                *reinterpret_cast<float2*>(op + (size_t)(r0 + 8) * 256 + cc) =
                    make_float2(d[mt][nt][2], d[mt][nt][3]);
            }
        }
    }
}

extern "C" void kernel_launch(void* const* d_in, const int* in_sizes, int n_in,
                              void* d_out, int out_size) {
    (void)in_sizes; (void)n_in; (void)out_size;
    const float* x  = (const float*)d_in[0];
    const float* wr = (const float*)d_in[1];
    const float* wi = (const float*)d_in[2];
    float* out = (float*)d_out;

    k_tw  <<<1, 256>>>();
    k_tw2 <<<256, 64>>>();
    k_wt  <<<dim3(128, 32), 256>>>(wr, wi);
    k_fwdW<<<1024, 256>>>(x);
    k_fwdH<<<1024, 256>>>();
    k_mix <<<1024, 256>>>();
    k_invH<<<1024, 256>>>();
    k_invW<<<dim3(256, 2, 4), 256>>>(out);
}